// round 3
// baseline (speedup 1.0000x reference)
#include <cuda_runtime.h>

// ---------------------------------------------------------------------------
// Sparse2x4Conv2d: grouped 3x3 conv (B=32, CIN=256, 56x56, COUT=256, groups=2)
// with per-quadruplet 2:4 weight masking selected by hard gumbel-softmax.
// Forward value of the straight-through mask == the argmax pattern exactly
// (up to 1 ulp), so we compute mask = PATTERNS[argmax(cw+g)] directly.
//
// Kernel 1: build masked weights, transposed to [g][c][kh*3+kw][oc] layout.
// Kernel 2: direct conv, fp32, smem-tiled, register-blocked (4 oc x 7 px).
// ---------------------------------------------------------------------------

#define GROUPS 2
#define CG     128      // cin per group
#define OCG    128      // cout per group
#define HW     56
#define INF    1152     // CG * 9
#define QN     73728    // quadruplets

// conv tiling
#define OC_T   64       // oc per block
#define TH     4        // output rows per block
#define TW     28       // output cols per block (2 tiles cover 56)
#define KC     8        // channels per K chunk
#define IN_W   32       // padded smem input row width (need 30)
#define IN_ROWS 6       // TH + 2

// transposed masked weights: [g][c][t][oc]  (2*128*9*128 floats = 1.18 MB)
__device__ float g_Wt[GROUPS * CG * 9 * OCG];

// ---------------------------------------------------------------------------
// Kernel 1: per-quadruplet argmax over (choice_weights + gumbels), apply the
// selected 2:4 pattern to 4 consecutive weights, scatter into g_Wt transposed.
// ---------------------------------------------------------------------------
__global__ void mask_weights_kernel(const float* __restrict__ Ws,
                                    const float* __restrict__ cw,
                                    const float* __restrict__ gb,
                                    const float* __restrict__ mp) {
    int q = blockIdx.x * blockDim.x + threadIdx.x;
    if (q >= QN) return;

    // argmax over 6 logits (first-max wins, matching jnp.argmax)
    float best = cw[q * 6 + 0] + gb[q * 6 + 0];
    int idx = 0;
#pragma unroll
    for (int j = 1; j < 6; j++) {
        float v = cw[q * 6 + j] + gb[q * 6 + j];
        if (v > best) { best = v; idx = j; }
    }

    const float4 m  = *reinterpret_cast<const float4*>(mp + idx * 4);
    const float4 w4 = *reinterpret_cast<const float4*>(Ws + q * 4);
    float wm[4] = { w4.x * m.x, w4.y * m.y, w4.z * m.z, w4.w * m.w };

    int e0  = q * 4;                  // flat index into (G, OCG, INF)
    int g   = e0 / (OCG * INF);
    int rem = e0 % (OCG * INF);
    int oc  = rem / INF;
    int i0  = rem % INF;

#pragma unroll
    for (int k = 0; k < 4; k++) {
        int i = i0 + k;
        int c = i / 9;                // channel within group
        int t = i % 9;                // kh*3+kw
        g_Wt[((g * CG + c) * 9 + t) * OCG + oc] = wm[k];
    }
}

// ---------------------------------------------------------------------------
// Kernel 2: direct conv.
// Block: 64 oc x (4 x 28) pixels for one (b, g). 256 threads.
// Thread: pix_t = tid%16 (pixels p = pix_t + 16*i, i<7), oc_t = tid/16
//         (oc = oc_t*4 + j, j<4). 28 fp32 accumulators.
// ---------------------------------------------------------------------------
__global__ __launch_bounds__(256)
void conv_kernel(const float* __restrict__ x, float* __restrict__ out) {
    __shared__ __align__(16) float s_in[KC * IN_ROWS * IN_W];   // 1536 floats
    __shared__ __align__(16) float s_w[KC * 9 * OC_T];          // 4608 floats

    const int tid   = threadIdx.x;
    const int pix_t = tid & 15;
    const int oc_t  = tid >> 4;

    const int sp = blockIdx.x;                // 0..27
    const int bh = sp >> 1;                   // 0..13
    const int bw = sp & 1;                    // 0..1
    const int h0 = bh * TH;
    const int w0 = bw * TW;
    const int oc_base = blockIdx.y * OC_T;    // 0 or 64
    const int bz = blockIdx.z;                // 0..63
    const int b  = bz >> 1;
    const int g  = bz & 1;

    const float* xg = x + (b * 256 + g * 128) * (HW * HW);
    const float* wg = g_Wt + g * (CG * 9 * OCG) + oc_base;

    // per-thread pixel bases inside the padded smem tile
    int base[7];
#pragma unroll
    for (int i = 0; i < 7; i++) {
        int p = pix_t + 16 * i;               // 0..111
        base[i] = (p / 28) * IN_W + (p % 28);
    }

    float acc[4][7];
#pragma unroll
    for (int j = 0; j < 4; j++)
#pragma unroll
        for (int i = 0; i < 7; i++) acc[j][i] = 0.0f;

    for (int c0 = 0; c0 < CG; c0 += KC) {
        __syncthreads();

        // ---- stage input halo tile: KC channels x 6 rows x 30 cols ----
        for (int i = tid; i < KC * IN_ROWS * 30; i += 256) {
            int kc  = i / (IN_ROWS * 30);
            int rem = i % (IN_ROWS * 30);
            int r   = rem / 30;
            int cc  = rem % 30;
            int h = h0 - 1 + r;
            int w = w0 - 1 + cc;
            float v = 0.0f;
            if ((unsigned)h < HW && (unsigned)w < HW)
                v = __ldg(xg + (c0 + kc) * (HW * HW) + h * HW + w);
            s_in[kc * (IN_ROWS * IN_W) + r * IN_W + cc] = v;
        }

        // ---- stage weights: [kc][t][oc], oc contiguous (coalesced, no STS conflicts)
        for (int j = tid; j < OC_T * KC * 9; j += 256) {
            int oc = j & (OC_T - 1);
            int kt = j >> 6;                  // kc*9 + t, 0..71
            s_w[kt * OC_T + oc] = wg[(c0 * 9 + kt) * OCG + oc];
        }

        __syncthreads();

        // ---- compute ----
#pragma unroll
        for (int kc = 0; kc < KC; kc++) {
            const float* wk = s_w + kc * (9 * OC_T) + oc_t * 4;
            const float* ik = s_in + kc * (IN_ROWS * IN_W);
#pragma unroll
            for (int t = 0; t < 9; t++) {
                float4 wv = *reinterpret_cast<const float4*>(wk + t * OC_T);
                const int off = (t / 3) * IN_W + (t % 3);
#pragma unroll
                for (int i = 0; i < 7; i++) {
                    float xv = ik[off + base[i]];
                    acc[0][i] = fmaf(wv.x, xv, acc[0][i]);
                    acc[1][i] = fmaf(wv.y, xv, acc[1][i]);
                    acc[2][i] = fmaf(wv.z, xv, acc[2][i]);
                    acc[3][i] = fmaf(wv.w, xv, acc[3][i]);
                }
            }
        }
    }

    // ---- store: lanes (pix_t) vary fastest -> coalesced ----
    const int ob = (b * 256 + g * 128 + oc_base + oc_t * 4) * (HW * HW);
#pragma unroll
    for (int j = 0; j < 4; j++) {
#pragma unroll
        for (int i = 0; i < 7; i++) {
            int p = pix_t + 16 * i;
            out[ob + j * (HW * HW) + (h0 + p / 28) * HW + (w0 + p % 28)] = acc[j][i];
        }
    }
}

// ---------------------------------------------------------------------------
// inputs (metadata order): x, Ws, choice_weights, gumbels, masking_patterns
// ---------------------------------------------------------------------------
extern "C" void kernel_launch(void* const* d_in, const int* in_sizes, int n_in,
                              void* d_out, int out_size) {
    const float* x  = (const float*)d_in[0];
    const float* Ws = (const float*)d_in[1];
    const float* cw = (const float*)d_in[2];
    const float* gb = (const float*)d_in[3];
    const float* mp = (const float*)d_in[4];
    float* out = (float*)d_out;

    mask_weights_kernel<<<(QN + 255) / 256, 256>>>(Ws, cw, gb, mp);

    dim3 grid(28, 2, 64);   // spatial tiles x oc tiles x (b,g)
    conv_kernel<<<grid, 256>>>(x, out);
}

// round 12
// speedup vs baseline: 2.0582x; 2.0582x over previous
#include <cuda_runtime.h>
#include <cuda_fp16.h>
#include <cstdint>

// ---------------------------------------------------------------------------
// Sparse2x4Conv2d via warp-level tensor-core implicit GEMM (mma.sync fp16,
// hi/lo split, fp32 accum). tcgen05 is unavailable: the harness PTX targets
// compute_103 (no 'a'), which rejects all arch-'a' instructions.
//   mask = PATTERNS[argmax(cw+gumbel)]  (exact forward of straight-through)
//   y[b,g,oc,px] = sum_k W[g,oc,k] * patch[b,g,k,px]
//   A*B ~= Ah*Bh + Ah*Bl + Al*Bh  (fp16 hi/lo, residual ~2^-23)
// R11 fix: A smem copy covered only 1024 of 1152 uint4 per tile (AP=72
// padding grew the tile to 18432B); oc rows 114-127 computed on garbage.
// ---------------------------------------------------------------------------

#define HW      56
#define PIX     3136
#define GROUPS  2
#define CG      128
#define OCG     128
#define INF     1152
#define QN      73728
#define NCHUNK  18          // K chunks of 64
#define NT      112         // N tile: 2 output rows
#define AP      72          // padded k-stride (fp16) -> conflict-free ldmatrix
#define A_U4    1152        // uint4 per A tile: 128 * 72 * 2 / 16

// smem byte offsets
#define SO_AHI   0
#define SO_ALO   (128 * AP * 2)                 // 18432
#define SO_BHI   (SO_ALO + 128 * AP * 2)        // 36864
#define SO_BLO   (SO_BHI + NT * AP * 2)         // 52992
#define SO_STAGE (SO_BLO + NT * AP * 2)         // 69120
#define STAGE_FLOATS (9 * 4 * 58)               // 2088
#define SMEM_TOTAL   (SO_STAGE + STAGE_FLOATS * 4)  // 77472

// pre-split masked weights, padded [g][chunk][128 oc][AP k] fp16
__device__ __align__(16) __half g_Ahi[(size_t)GROUPS * NCHUNK * 128 * AP];
__device__ __align__(16) __half g_Alo[(size_t)GROUPS * NCHUNK * 128 * AP];

static __device__ __forceinline__ uint32_t smem_u32(const void* p) {
    return (uint32_t)__cvta_generic_to_shared(p);
}
static __device__ __forceinline__ void ldsm_x4(uint32_t* r, uint32_t a) {
    asm volatile("ldmatrix.sync.aligned.m8n8.x4.shared.b16 {%0,%1,%2,%3}, [%4];"
                 : "=r"(r[0]), "=r"(r[1]), "=r"(r[2]), "=r"(r[3]) : "r"(a));
}
static __device__ __forceinline__ void ldsm_x2(uint32_t* r, uint32_t a) {
    asm volatile("ldmatrix.sync.aligned.m8n8.x2.shared.b16 {%0,%1}, [%2];"
                 : "=r"(r[0]), "=r"(r[1]) : "r"(a));
}
static __device__ __forceinline__ void mma16816(float* c, const uint32_t* a,
                                                const uint32_t* b) {
    asm volatile(
        "mma.sync.aligned.m16n8k16.row.col.f32.f16.f16.f32 "
        "{%0,%1,%2,%3}, {%4,%5,%6,%7}, {%8,%9}, {%0,%1,%2,%3};"
        : "+f"(c[0]), "+f"(c[1]), "+f"(c[2]), "+f"(c[3])
        : "r"(a[0]), "r"(a[1]), "r"(a[2]), "r"(a[3]), "r"(b[0]), "r"(b[1]));
}

// ---------------------------------------------------------------------------
// Kernel 1: argmax-masked weights -> fp16 hi/lo, padded GEMM-ready layout.
// ---------------------------------------------------------------------------
__global__ void mask_split_kernel(const float* __restrict__ Ws,
                                  const float* __restrict__ cw,
                                  const float* __restrict__ gb,
                                  const float* __restrict__ mp) {
    int q = blockIdx.x * blockDim.x + threadIdx.x;
    if (q >= QN) return;

    float best = cw[q * 6 + 0] + gb[q * 6 + 0];
    int idx = 0;
#pragma unroll
    for (int j = 1; j < 6; j++) {
        float v = cw[q * 6 + j] + gb[q * 6 + j];
        if (v > best) { best = v; idx = j; }
    }
    const float4 m  = *reinterpret_cast<const float4*>(mp + idx * 4);
    const float4 w4 = *reinterpret_cast<const float4*>(Ws + q * 4);
    float wm[4] = { w4.x * m.x, w4.y * m.y, w4.z * m.z, w4.w * m.w };

    int e0  = q * 4;
    int g   = e0 / (OCG * INF);
    int rem = e0 % (OCG * INF);
    int oc  = rem / INF;
    int i0  = rem % INF;
    int chunk = i0 >> 6;
    int kl    = i0 & 63;          // multiple of 4, never straddles a chunk

    unsigned short h[4], l[4];
#pragma unroll
    for (int k = 0; k < 4; k++) {
        __half hb = __float2half_rn(wm[k]);
        __half lb = __float2half_rn(wm[k] - __half2float(hb));
        h[k] = __half_as_ushort(hb);
        l[k] = __half_as_ushort(lb);
    }
    size_t base = ((size_t)(g * NCHUNK + chunk) * 128 + oc) * AP + kl;  // fp16 units
    uint2 hp = make_uint2(((uint32_t)h[1] << 16) | h[0], ((uint32_t)h[3] << 16) | h[2]);
    uint2 lp = make_uint2(((uint32_t)l[1] << 16) | l[0], ((uint32_t)l[3] << 16) | l[2]);
    *reinterpret_cast<uint2*>(&g_Ahi[base]) = hp;
    *reinterpret_cast<uint2*>(&g_Alo[base]) = lp;
}

// ---------------------------------------------------------------------------
// Kernel 2: per-CTA 128(oc) x 112(px), K = 18 x 64, 3 split terms on HMMA.
// Warps: 4 (m) x 2 (n); each warp 32 m x 56 n = 2 x 7 fragments.
// ---------------------------------------------------------------------------
__global__ __launch_bounds__(256)
void conv_mma_kernel(const float* __restrict__ x, float* __restrict__ out) {
    extern __shared__ __align__(16) uint8_t sm[];
    const uint32_t smb = smem_u32(sm);

    const int tid  = threadIdx.x;
    const int wid  = tid >> 5;
    const int lane = tid & 31;

    const int tile = blockIdx.x;          // 0..27 (2 output rows)
    const int bz   = blockIdx.y;          // 0..63
    const int b    = bz >> 1;
    const int g    = bz & 1;
    const int h0img = tile * 2;

    const float* xg = x + (size_t)(b * 256 + g * 128) * PIX;
    float* stage = reinterpret_cast<float*>(sm + SO_STAGE);

    // warp tile position
    const int wm = wid & 3;               // m0 = wm*32
    const int wn = wid >> 2;              // n0 = wn*56
    const int m0 = wm * 32;
    const int n0 = wn * 56;

    // ldmatrix per-thread byte offsets (within A/B tiles)
    const int aoff = (m0 + (lane & 15)) * (AP * 2) + (lane >> 4) * 16;
    const int boff = (n0 + (lane & 7)) * (AP * 2) + ((lane >> 3) & 1) * 16;

    // B-build constants
    const int kp    = tid & 31;           // k-pair: k = 2*kp, 2*kp+1
    const int ng    = tid >> 5;           // 8 groups of 14 pixels
    const int ph    = ng >> 2;
    const int pw0   = ng * 14 - ph * 56;
    const int nbase = ng * 14;

    float c[2][7][4];
#pragma unroll
    for (int i = 0; i < 2; i++)
#pragma unroll
        for (int j = 0; j < 7; j++)
#pragma unroll
            for (int k = 0; k < 4; k++) c[i][j][k] = 0.0f;

    for (int chunk = 0; chunk < NCHUNK; chunk++) {
        __syncthreads();   // previous compute done reading A/B/stage

        const int cbeg = (chunk * 64) / 9;

        // ---- stage input halo: 9 ch x 4 rows x 58 cols fp32, zero-padded ----
        for (int i = tid; i < STAGE_FLOATS; i += 256) {
            int ci = i / 232;
            int r2 = i - ci * 232;
            int rr = r2 / 58;
            int cc = r2 - rr * 58;
            int ch = cbeg + ci;
            int h  = h0img - 1 + rr;
            int w  = cc - 1;
            float v = 0.0f;
            if (ch < CG && (unsigned)h < HW && (unsigned)w < HW)
                v = __ldg(xg + ch * PIX + h * HW + w);
            stage[i] = v;
        }

        // ---- copy pre-split A tiles (hi & lo), 1152 uint4 each ----
        {
            const uint4* sh = reinterpret_cast<const uint4*>(
                g_Ahi + (size_t)(g * NCHUNK + chunk) * 128 * AP);
            const uint4* sl = reinterpret_cast<const uint4*>(
                g_Alo + (size_t)(g * NCHUNK + chunk) * 128 * AP);
            uint4* dh = reinterpret_cast<uint4*>(sm + SO_AHI);
            uint4* dl = reinterpret_cast<uint4*>(sm + SO_ALO);
#pragma unroll
            for (int i = 0; i < 5; i++) {            // 5*256 = 1280 >= 1152
                int j = tid + i * 256;
                if (j < A_U4) { dh[j] = sh[j]; dl[j] = sl[j]; }
            }
        }
        __syncthreads();

        // ---- build B tiles [n][k] fp16 hi/lo from stage ----
        {
            const int k0 = chunk * 64 + kp * 2;
            const int c0 = k0 / 9,  t0 = k0 - c0 * 9;
            const int k1 = k0 + 1;
            const int c1 = k1 / 9,  t1 = k1 - c1 * 9;
            const int kh0 = t0 / 3, kw0 = t0 - kh0 * 3;
            const int kh1 = t1 / 3, kw1 = t1 - kh1 * 3;
            const int a0 = (c0 - cbeg) * 232 + (ph + kh0) * 58 + pw0 + kw0;
            const int a1 = (c1 - cbeg) * 232 + (ph + kh1) * 58 + pw0 + kw1;
#pragma unroll
            for (int j = 0; j < 14; j++) {
                float v0 = stage[a0 + j];
                float v1 = stage[a1 + j];
                __half h0 = __float2half_rn(v0);
                __half h1 = __float2half_rn(v1);
                __half l0 = __float2half_rn(v0 - __half2float(h0));
                __half l1 = __float2half_rn(v1 - __half2float(h1));
                uint32_t hp = ((uint32_t)__half_as_ushort(h1) << 16) |
                              __half_as_ushort(h0);
                uint32_t lp = ((uint32_t)__half_as_ushort(l1) << 16) |
                              __half_as_ushort(l0);
                int off = (nbase + j) * (AP * 2) + kp * 4;
                *reinterpret_cast<uint32_t*>(sm + SO_BHI + off) = hp;
                *reinterpret_cast<uint32_t*>(sm + SO_BLO + off) = lp;
            }
        }
        __syncthreads();

        // ---- tensor-core compute: 4 k-steps x (2m x 7n) x 3 terms ----
#pragma unroll
        for (int ks = 0; ks < 4; ks++) {
            const int kb = ks * 32;       // k0*2 bytes
            uint32_t ah[2][4], al[2][4];
            ldsm_x4(ah[0], smb + SO_AHI + aoff + kb);
            ldsm_x4(ah[1], smb + SO_AHI + aoff + kb + 16 * AP * 2);
            ldsm_x4(al[0], smb + SO_ALO + aoff + kb);
            ldsm_x4(al[1], smb + SO_ALO + aoff + kb + 16 * AP * 2);
#pragma unroll
            for (int nt = 0; nt < 7; nt++) {
                uint32_t bh[2], bl[2];
                ldsm_x2(bh, smb + SO_BHI + boff + kb + nt * (8 * AP * 2));
                ldsm_x2(bl, smb + SO_BLO + boff + kb + nt * (8 * AP * 2));
                mma16816(c[0][nt], ah[0], bh);
                mma16816(c[1][nt], ah[1], bh);
                mma16816(c[0][nt], ah[0], bl);
                mma16816(c[1][nt], ah[1], bl);
                mma16816(c[0][nt], al[0], bh);
                mma16816(c[1][nt], al[1], bh);
            }
        }
    }

    // ---- epilogue: direct STG, each lane-quad writes full 32B sectors ----
    const size_t obase = (size_t)(b * 256 + g * 128) * PIX + (size_t)tile * NT;
    const int r0 = m0 + (lane >> 2);
    const int nn = n0 + 2 * (lane & 3);
#pragma unroll
    for (int mt = 0; mt < 2; mt++) {
#pragma unroll
        for (int nt = 0; nt < 7; nt++) {
            const int r = r0 + mt * 16;
            const int n = nn + nt * 8;
            *reinterpret_cast<float2*>(out + obase + (size_t)r * PIX + n) =
                make_float2(c[mt][nt][0], c[mt][nt][1]);
            *reinterpret_cast<float2*>(out + obase + (size_t)(r + 8) * PIX + n) =
                make_float2(c[mt][nt][2], c[mt][nt][3]);
        }
    }
}

// ---------------------------------------------------------------------------
// inputs: x, Ws, choice_weights, gumbels, masking_patterns
// ---------------------------------------------------------------------------
extern "C" void kernel_launch(void* const* d_in, const int* in_sizes, int n_in,
                              void* d_out, int out_size) {
    const float* x  = (const float*)d_in[0];
    const float* Ws = (const float*)d_in[1];
    const float* cw = (const float*)d_in[2];
    const float* gb = (const float*)d_in[3];
    const float* mp = (const float*)d_in[4];
    float* out = (float*)d_out;

    cudaFuncSetAttribute(conv_mma_kernel,
                         cudaFuncAttributeMaxDynamicSharedMemorySize, SMEM_TOTAL);

    mask_split_kernel<<<(QN + 255) / 256, 256>>>(Ws, cw, gb, mp);

    dim3 grid(28, 64);     // spatial tiles x (b,g)
    conv_mma_kernel<<<grid, 256, SMEM_TOTAL>>>(x, out);
}

// round 13
// speedup vs baseline: 2.7273x; 1.3251x over previous
#include <cuda_runtime.h>
#include <cuda_fp16.h>
#include <cstdint>

// ---------------------------------------------------------------------------
// Sparse2x4Conv2d via shift-GEMM on mma.sync fp16 hi/lo (fp32 accum).
//   conv3x3 = sum over 9 taps of GEMM: y[oc][px] += Wtap[oc][c] * x[px+D][c]
// x is pre-transposed to [bg][px][c] fp16 hi/lo, so B tiles load directly
// with cp.async (whole-row zero-fill for halo/edge pixels). No im2col build,
// no fp32->fp16 conversion in the hot loop.
//   A*B ~= Ah*Bh + Ah*Bl + Al*Bh   (residual ~2^-23)
// ---------------------------------------------------------------------------

#define HW      56
#define PIX     3136
#define GROUPS  2
#define CG      128
#define OCG     128
#define INF     1152
#define QN      73728
#define NCHUNK  18          // 9 taps x 2 channel-halves of 64
#define NT      112         // N tile: 2 output rows
#define AP      72          // k-row stride in halves (144B) -> conflict-free ldsm

// smem byte offsets (single buffer; 2 CTAs/SM overlap hides the wait)
#define SO_AHI   0                       // 128 x 144
#define SO_ALO   18432
#define SO_BHI   36864                   // 112 x 144
#define SO_BLO   52992
#define SMEM_TOTAL 69120

// pre-split weights, tap-major: [g][chunk][oc=128][c=64] fp16
__device__ __align__(16) __half g_Whi[(size_t)GROUPS * NCHUNK * 128 * 64];
__device__ __align__(16) __half g_Wlo[(size_t)GROUPS * NCHUNK * 128 * 64];
// transposed input: [bg=64][px=3136][c=128] fp16 hi/lo (51.4 MB each)
__device__ __align__(16) __half g_xThi[(size_t)64 * PIX * 128];
__device__ __align__(16) __half g_xTlo[(size_t)64 * PIX * 128];

static __device__ __forceinline__ uint32_t smem_u32(const void* p) {
    return (uint32_t)__cvta_generic_to_shared(p);
}
static __device__ __forceinline__ void cp16(uint32_t dst, const __half* src, int sz) {
    asm volatile("cp.async.cg.shared.global [%0], [%1], 16, %2;"
                 :: "r"(dst), "l"(src), "r"(sz) : "memory");
}
static __device__ __forceinline__ void ldsm_x4(uint32_t* r, uint32_t a) {
    asm volatile("ldmatrix.sync.aligned.m8n8.x4.shared.b16 {%0,%1,%2,%3}, [%4];"
                 : "=r"(r[0]), "=r"(r[1]), "=r"(r[2]), "=r"(r[3]) : "r"(a));
}
static __device__ __forceinline__ void ldsm_x2(uint32_t* r, uint32_t a) {
    asm volatile("ldmatrix.sync.aligned.m8n8.x2.shared.b16 {%0,%1}, [%2];"
                 : "=r"(r[0]), "=r"(r[1]) : "r"(a));
}
static __device__ __forceinline__ void mma16816(float* c, const uint32_t* a,
                                                const uint32_t* b) {
    asm volatile(
        "mma.sync.aligned.m16n8k16.row.col.f32.f16.f16.f32 "
        "{%0,%1,%2,%3}, {%4,%5,%6,%7}, {%8,%9}, {%0,%1,%2,%3};"
        : "+f"(c[0]), "+f"(c[1]), "+f"(c[2]), "+f"(c[3])
        : "r"(a[0]), "r"(a[1]), "r"(a[2]), "r"(a[3]), "r"(b[0]), "r"(b[1]));
}

// ---------------------------------------------------------------------------
// Kernel 0: transpose x [bg][c][px] fp32 -> xT [bg][px][c] fp16 hi/lo.
// ---------------------------------------------------------------------------
__global__ __launch_bounds__(256)
void xt_kernel(const float* __restrict__ x) {
    __shared__ float s[128][33];
    const int tid = threadIdx.x;
    const int bg  = blockIdx.y;
    const int px0 = blockIdx.x * 32;
    const float* xb = x + (size_t)bg * 128 * PIX;

#pragma unroll
    for (int i = 0; i < 16; i++) {
        int idx = tid + i * 256;
        int c = idx >> 5, p = idx & 31;
        s[c][p] = xb[(size_t)c * PIX + px0 + p];
    }
    __syncthreads();
#pragma unroll
    for (int i = 0; i < 16; i++) {
        int idx = tid + i * 256;
        int p = idx >> 7, c = idx & 127;
        float v = s[c][p];
        __half h = __float2half_rn(v);
        __half l = __float2half_rn(v - __half2float(h));
        size_t o = ((size_t)bg * PIX + px0 + p) * 128 + c;
        g_xThi[o] = h;
        g_xTlo[o] = l;
    }
}

// ---------------------------------------------------------------------------
// Kernel 1: argmax-masked weights -> fp16 hi/lo, tap-major GEMM layout.
//   element (g, oc, i = c*9 + t):  chunk = t*2 + (c>=64), col = c&63
// ---------------------------------------------------------------------------
__global__ void mask_split_kernel(const float* __restrict__ Ws,
                                  const float* __restrict__ cw,
                                  const float* __restrict__ gb,
                                  const float* __restrict__ mp) {
    int q = blockIdx.x * blockDim.x + threadIdx.x;
    if (q >= QN) return;

    float best = cw[q * 6 + 0] + gb[q * 6 + 0];
    int idx = 0;
#pragma unroll
    for (int j = 1; j < 6; j++) {
        float v = cw[q * 6 + j] + gb[q * 6 + j];
        if (v > best) { best = v; idx = j; }
    }
    const float4 m  = *reinterpret_cast<const float4*>(mp + idx * 4);
    const float4 w4 = *reinterpret_cast<const float4*>(Ws + q * 4);
    float wm[4] = { w4.x * m.x, w4.y * m.y, w4.z * m.z, w4.w * m.w };

    int e0  = q * 4;
    int g   = e0 / (OCG * INF);
    int rem = e0 % (OCG * INF);
    int oc  = rem / INF;
    int i0  = rem % INF;

#pragma unroll
    for (int k = 0; k < 4; k++) {
        int i = i0 + k;
        int c = i / 9;
        int t = i - c * 9;
        int chunk = t * 2 + (c >> 6);
        int col   = c & 63;
        __half hb = __float2half_rn(wm[k]);
        __half lb = __float2half_rn(wm[k] - __half2float(hb));
        size_t o = (((size_t)(g * NCHUNK) + chunk) * 128 + oc) * 64 + col;
        g_Whi[o] = hb;
        g_Wlo[o] = lb;
    }
}

// ---------------------------------------------------------------------------
// Kernel 2: per-CTA 128(oc) x 112(px), 18 chunks, cp.async fill, HMMA.
// ---------------------------------------------------------------------------
__global__ __launch_bounds__(256, 2)
void conv_mma_kernel(const float* __restrict__ x, float* __restrict__ out) {
    extern __shared__ __align__(128) uint8_t sm[];
    const uint32_t smb = smem_u32(sm);

    const int tid  = threadIdx.x;
    const int wid  = tid >> 5;
    const int lane = tid & 31;

    const int tile  = blockIdx.x;         // 0..27 (2 output rows)
    const int bz    = blockIdx.y;         // bg = b*2+g, matches xT layout
    const int b     = bz >> 1;
    const int g     = bz & 1;
    const int h0img = tile * 2;

    // warp tile position: 4 (m) x 2 (n)
    const int m0 = (wid & 3) * 32;
    const int n0 = (wid >> 2) * 56;
    const int aoff = (m0 + (lane & 15)) * (AP * 2) + (lane >> 4) * 16;
    const int boff = (n0 + (lane & 7)) * (AP * 2) + ((lane >> 3) & 1) * 16;

    // cp.async task mapping: seg = 16B segment, rid = row group
    const int seg = tid & 7;
    const int rid = tid >> 3;             // 0..31
    int hhB[4], wwB[4];
#pragma unroll
    for (int i = 0; i < 4; i++) {
        int r = rid + 32 * i;
        hhB[i] = (r >= 56);
        wwB[i] = r - hhB[i] * 56;
    }

    float c[2][7][4];
#pragma unroll
    for (int i = 0; i < 2; i++)
#pragma unroll
        for (int j = 0; j < 7; j++)
#pragma unroll
            for (int k = 0; k < 4; k++) c[i][j][k] = 0.0f;

    const __half* xh_base = g_xThi + (size_t)bz * PIX * 128;
    const __half* xl_base = g_xTlo + (size_t)bz * PIX * 128;

    for (int chunk = 0; chunk < NCHUNK; chunk++) {
        __syncthreads();                  // all warps done reading smem

        const int t     = chunk >> 1;     // tap 0..8
        const int chalf = chunk & 1;
        const int kh = t / 3, kw = t - kh * 3;

        // ---- A: weights, tap-major contiguous ----
        const __half* wh = g_Whi + (size_t)(g * NCHUNK + chunk) * 128 * 64;
        const __half* wl = g_Wlo + (size_t)(g * NCHUNK + chunk) * 128 * 64;
#pragma unroll
        for (int i = 0; i < 4; i++) {
            int r = rid + 32 * i;
            cp16(smb + SO_AHI + r * 144 + seg * 16, wh + r * 64 + seg * 8, 16);
            cp16(smb + SO_ALO + r * 144 + seg * 16, wl + r * 64 + seg * 8, 16);
        }

        // ---- B: shifted pixel rows from xT, zero-fill OOB rows ----
#pragma unroll
        for (int i = 0; i < 4; i++) {
            int r = rid + 32 * i;
            if (r < NT) {
                int hp = h0img + hhB[i] + kh - 1;
                int wp = wwB[i] + kw - 1;
                bool ok = ((unsigned)hp < HW) & ((unsigned)wp < HW);
                size_t po = ok ? ((size_t)(hp * HW + wp) * 128 + chalf * 64) : 0;
                int sz = ok ? 16 : 0;
                cp16(smb + SO_BHI + r * 144 + seg * 16, xh_base + po + seg * 8, sz);
                cp16(smb + SO_BLO + r * 144 + seg * 16, xl_base + po + seg * 8, sz);
            }
        }
        asm volatile("cp.async.commit_group;" ::: "memory");
        asm volatile("cp.async.wait_group 0;" ::: "memory");
        __syncthreads();

        // ---- tensor-core compute: 4 k-steps x (2m x 7n) x 3 terms ----
#pragma unroll
        for (int ks = 0; ks < 4; ks++) {
            const int kb = ks * 32;
            uint32_t ah[2][4], al[2][4];
            ldsm_x4(ah[0], smb + SO_AHI + aoff + kb);
            ldsm_x4(ah[1], smb + SO_AHI + aoff + kb + 16 * AP * 2);
            ldsm_x4(al[0], smb + SO_ALO + aoff + kb);
            ldsm_x4(al[1], smb + SO_ALO + aoff + kb + 16 * AP * 2);
#pragma unroll
            for (int nt = 0; nt < 7; nt++) {
                uint32_t bh[2], bl[2];
                ldsm_x2(bh, smb + SO_BHI + boff + kb + nt * (8 * AP * 2));
                ldsm_x2(bl, smb + SO_BLO + boff + kb + nt * (8 * AP * 2));
                mma16816(c[0][nt], ah[0], bh);
                mma16816(c[1][nt], ah[1], bh);
                mma16816(c[0][nt], ah[0], bl);
                mma16816(c[1][nt], ah[1], bl);
                mma16816(c[0][nt], al[0], bh);
                mma16816(c[1][nt], al[1], bh);
            }
        }
    }

    // ---- epilogue: direct STG, lane-quads write full 32B sectors ----
    const size_t obase = (size_t)(b * 256 + g * 128) * PIX + (size_t)tile * NT;
    const int r0 = m0 + (lane >> 2);
    const int nn = n0 + 2 * (lane & 3);
#pragma unroll
    for (int mt = 0; mt < 2; mt++) {
#pragma unroll
        for (int nt = 0; nt < 7; nt++) {
            const int r = r0 + mt * 16;
            const int n = nn + nt * 8;
            *reinterpret_cast<float2*>(out + obase + (size_t)r * PIX + n) =
                make_float2(c[mt][nt][0], c[mt][nt][1]);
            *reinterpret_cast<float2*>(out + obase + (size_t)(r + 8) * PIX + n) =
                make_float2(c[mt][nt][2], c[mt][nt][3]);
        }
    }
}

// ---------------------------------------------------------------------------
// inputs: x, Ws, choice_weights, gumbels, masking_patterns
// ---------------------------------------------------------------------------
extern "C" void kernel_launch(void* const* d_in, const int* in_sizes, int n_in,
                              void* d_out, int out_size) {
    const float* x  = (const float*)d_in[0];
    const float* Ws = (const float*)d_in[1];
    const float* cw = (const float*)d_in[2];
    const float* gb = (const float*)d_in[3];
    const float* mp = (const float*)d_in[4];
    float* out = (float*)d_out;

    cudaFuncSetAttribute(conv_mma_kernel,
                         cudaFuncAttributeMaxDynamicSharedMemorySize, SMEM_TOTAL);

    dim3 tgrid(PIX / 32, 64);
    xt_kernel<<<tgrid, 256>>>(x);
    mask_split_kernel<<<(QN + 255) / 256, 256>>>(Ws, cw, gb, mp);

    dim3 grid(28, 64);     // spatial tiles x (b,g)
    conv_mma_kernel<<<grid, 256, SMEM_TOTAL>>>(x, out);
}